// round 5
// baseline (speedup 1.0000x reference)
#include <cuda_runtime.h>
#include <cuda_bf16.h>

// Causal self-attention, B=1, S=4096, H=16, D=64, fp32.
// qkv layout: [S, 3, H, D] (batch 1 dropped). out: [S, H, D].
// Flash-attention style: BM=BN=64 tiles, 256 threads, 4x4 micro-tile/thread.
// Four padded fp32 tiles = 65 KB smem -> dynamic smem opt-in (static cap is 48 KB).

#define SEQ   4096
#define NH    16
#define HD    64
#define BM    64
#define BN    64
#define LDS_  (HD + 1)
#define NTHR  256
#define TOKST (3 * NH * HD)     // 3072 floats per token
#define LOG2E 1.4426950408889634f

#define SMEM_FLOATS (4 * BM * LDS_)
#define SMEM_BYTES  (SMEM_FLOATS * sizeof(float))

__global__ __launch_bounds__(NTHR, 3)
void attn_fwd_kernel(const float* __restrict__ qkv, float* __restrict__ out) {
    extern __shared__ float smem[];
    float (*Qs)[LDS_] = (float (*)[LDS_])(smem);
    float (*Ks)[LDS_] = (float (*)[LDS_])(smem + BM * LDS_);
    float (*Vs)[LDS_] = (float (*)[LDS_])(smem + 2 * BM * LDS_);
    float (*Ps)[LDS_] = (float (*)[LDS_])(smem + 3 * BM * LDS_);

    const int h  = blockIdx.y;
    const int qt = gridDim.x - 1 - blockIdx.x;   // longest blocks first
    const int q0 = qt * BM;
    const int tid = threadIdx.x;
    const int tx = tid & 15;
    const int ty = tid >> 4;
    const int r0 = ty * 4;
    const int c0 = tx * 4;

    const float scale = 0.125f;  // 1/sqrt(64)

    // ---- load Q tile (float4, pre-scaled) ----
    const float* qbase = qkv + (size_t)h * HD;
    for (int lin = tid; lin < BM * HD / 4; lin += NTHR) {
        int r = lin >> 4, d4 = (lin & 15) << 2;
        float4 v = *(const float4*)(qbase + (size_t)(q0 + r) * TOKST + d4);
        Qs[r][d4 + 0] = v.x * scale;
        Qs[r][d4 + 1] = v.y * scale;
        Qs[r][d4 + 2] = v.z * scale;
        Qs[r][d4 + 3] = v.w * scale;
    }

    float m_i[4], l_i[4], acc[4][4];
    #pragma unroll
    for (int i = 0; i < 4; i++) {
        m_i[i] = -1e30f; l_i[i] = 0.f;
        #pragma unroll
        for (int j = 0; j < 4; j++) acc[i][j] = 0.f;
    }

    __syncthreads();

    const float* kbase = qkv + (size_t)NH * HD     + (size_t)h * HD;
    const float* vbase = qkv + (size_t)2 * NH * HD + (size_t)h * HD;

    for (int kt = 0; kt <= qt; kt++) {
        const int k0 = kt * BN;

        // ---- load K,V tiles (float4 global reads) ----
        for (int lin = tid; lin < BN * HD / 4; lin += NTHR) {
            int r = lin >> 4, d4 = (lin & 15) << 2;
            size_t off = (size_t)(k0 + r) * TOKST + d4;
            float4 kv = *(const float4*)(kbase + off);
            float4 vv = *(const float4*)(vbase + off);
            Ks[r][d4 + 0] = kv.x; Ks[r][d4 + 1] = kv.y;
            Ks[r][d4 + 2] = kv.z; Ks[r][d4 + 3] = kv.w;
            Vs[r][d4 + 0] = vv.x; Vs[r][d4 + 1] = vv.y;
            Vs[r][d4 + 2] = vv.z; Vs[r][d4 + 3] = vv.w;
        }
        __syncthreads();

        // ---- S = Q * K^T, 4x4 per thread ----
        float s[4][4];
        #pragma unroll
        for (int i = 0; i < 4; i++)
            #pragma unroll
            for (int j = 0; j < 4; j++) s[i][j] = 0.f;

        #pragma unroll 4
        for (int d = 0; d < HD; d++) {
            float a[4], b[4];
            #pragma unroll
            for (int i = 0; i < 4; i++) a[i] = Qs[r0 + i][d];
            #pragma unroll
            for (int j = 0; j < 4; j++) b[j] = Ks[c0 + j][d];
            #pragma unroll
            for (int i = 0; i < 4; i++)
                #pragma unroll
                for (int j = 0; j < 4; j++) s[i][j] = fmaf(a[i], b[j], s[i][j]);
        }

        // ---- causal mask (diagonal tile only) ----
        if (kt == qt) {
            #pragma unroll
            for (int i = 0; i < 4; i++)
                #pragma unroll
                for (int j = 0; j < 4; j++)
                    if (k0 + c0 + j > q0 + r0 + i) s[i][j] = -1e30f;
        }

        // ---- online softmax; each row spans 16 consecutive lanes ----
        #pragma unroll
        for (int i = 0; i < 4; i++) {
            float rmax = s[i][0];
            #pragma unroll
            for (int j = 1; j < 4; j++) rmax = fmaxf(rmax, s[i][j]);
            #pragma unroll
            for (int off = 8; off >= 1; off >>= 1)
                rmax = fmaxf(rmax, __shfl_xor_sync(0xffffffffu, rmax, off));

            float m_new = fmaxf(m_i[i], rmax);
            float corr  = exp2f((m_i[i] - m_new) * LOG2E);
            m_i[i] = m_new;

            float rsum = 0.f;
            #pragma unroll
            for (int j = 0; j < 4; j++) {
                float p = exp2f((s[i][j] - m_new) * LOG2E);
                s[i][j] = p;
                rsum += p;
            }
            #pragma unroll
            for (int off = 8; off >= 1; off >>= 1)
                rsum += __shfl_xor_sync(0xffffffffu, rsum, off);

            l_i[i] = l_i[i] * corr + rsum;
            #pragma unroll
            for (int j = 0; j < 4; j++) acc[i][j] *= corr;
        }

        // ---- stage P to smem for the PV GEMM ----
        #pragma unroll
        for (int i = 0; i < 4; i++)
            #pragma unroll
            for (int j = 0; j < 4; j++)
                Ps[r0 + i][c0 + j] = s[i][j];
        __syncthreads();

        // ---- O += P * V ----
        #pragma unroll 4
        for (int ss = 0; ss < BN; ss++) {
            float a[4], b[4];
            #pragma unroll
            for (int i = 0; i < 4; i++) a[i] = Ps[r0 + i][ss];
            #pragma unroll
            for (int j = 0; j < 4; j++) b[j] = Vs[ss][c0 + j];
            #pragma unroll
            for (int i = 0; i < 4; i++)
                #pragma unroll
                for (int j = 0; j < 4; j++) acc[i][j] = fmaf(a[i], b[j], acc[i][j]);
        }
        __syncthreads();
    }

    // ---- normalize + write out[t][h][d] (float4) ----
    #pragma unroll
    for (int i = 0; i < 4; i++) {
        float inv = 1.f / l_i[i];
        int t = q0 + r0 + i;
        float* o = out + ((size_t)t * NH + h) * HD + c0;
        float4 w;
        w.x = acc[i][0] * inv; w.y = acc[i][1] * inv;
        w.z = acc[i][2] * inv; w.w = acc[i][3] * inv;
        *(float4*)o = w;
    }
}

extern "C" void kernel_launch(void* const* d_in, const int* in_sizes, int n_in,
                              void* d_out, int out_size) {
    (void)in_sizes; (void)n_in; (void)out_size;
    const float* qkv = (const float*)d_in[0];
    float* out = (float*)d_out;
    cudaError_t attr_rc = cudaFuncSetAttribute(
        attn_fwd_kernel, cudaFuncAttributeMaxDynamicSharedMemorySize, SMEM_BYTES);
    (void)attr_rc;  // idempotent; capture-legal (not a stream op, not an alloc)
    dim3 grid(SEQ / BM, NH);
    attn_fwd_kernel<<<grid, NTHR, SMEM_BYTES>>>(qkv, out);
}

// round 7
// speedup vs baseline: 3.2023x; 3.2023x over previous
#include <cuda_runtime.h>
#include <cuda_bf16.h>
#include <cstdint>

// Causal self-attention, B=1, S=4096, H=16, D=64, fp32 in/out.
// FA2-style mma.sync.m16n8k16 bf16 kernel with hi/lo split precision (3-term).
// BM=BN=64, 128 threads (4 warps), each warp owns 16 q-rows.
// qkv layout: [S, 3, H, D]; out: [S, H, D].

#define SEQ   4096
#define NH    16
#define HD    64
#define BM    64
#define BN    64
#define NTHR  128
#define TOKST 3072
// 0.125 * log2(e): scores land in log2 domain -> ex2
#define QSCALE 0.18033688011112042f

#define KP    72                 // smem row pitch in bf16 elements
#define KPB   144                // row pitch bytes (9 x 16B units -> ldmatrix conflict-free)

__device__ __forceinline__ uint32_t smem_u32(const void* p) {
    uint32_t a;
    asm("{ .reg .u64 t; cvta.to.shared.u64 t, %1; cvt.u32.u64 %0, t; }"
        : "=r"(a) : "l"(p));
    return a;
}
__device__ __forceinline__ float ex2(float x) {
    float y;
    asm("ex2.approx.f32 %0, %1;" : "=f"(y) : "f"(x));
    return y;
}
// split fp32 pair -> packed bf16x2 hi + bf16x2 residual lo
__device__ __forceinline__ void split2(float a, float b, uint32_t& hi, uint32_t& lo) {
    __nv_bfloat16 ah = __float2bfloat16(a), bh = __float2bfloat16(b);
    __nv_bfloat162 H = __halves2bfloat162(ah, bh);
    __nv_bfloat162 L = __halves2bfloat162(__float2bfloat16(a - __bfloat162float(ah)),
                                          __float2bfloat16(b - __bfloat162float(bh)));
    hi = *reinterpret_cast<uint32_t*>(&H);
    lo = *reinterpret_cast<uint32_t*>(&L);
}

#define LDSM4(r, addr) \
    asm volatile("ldmatrix.sync.aligned.m8n8.x4.shared.b16 {%0,%1,%2,%3}, [%4];" \
        : "=r"((r)[0]), "=r"((r)[1]), "=r"((r)[2]), "=r"((r)[3]) : "r"(addr))
#define LDSM4T(r, addr) \
    asm volatile("ldmatrix.sync.aligned.m8n8.x4.trans.shared.b16 {%0,%1,%2,%3}, [%4];" \
        : "=r"((r)[0]), "=r"((r)[1]), "=r"((r)[2]), "=r"((r)[3]) : "r"(addr))
// D += A*B  (in-place f32 accum, bf16 inputs)
#define MMA(d, a, b) \
    asm volatile("mma.sync.aligned.m16n8k16.row.col.f32.bf16.bf16.f32 " \
        "{%0,%1,%2,%3}, {%4,%5,%6,%7}, {%8,%9}, {%0,%1,%2,%3};" \
        : "+f"((d)[0]), "+f"((d)[1]), "+f"((d)[2]), "+f"((d)[3]) \
        : "r"((a)[0]), "r"((a)[1]), "r"((a)[2]), "r"((a)[3]), \
          "r"((b)[0]), "r"((b)[1]))

__global__ __launch_bounds__(NTHR)
void attn_mma_kernel(const float* __restrict__ qkv, float* __restrict__ out) {
    // K hi/lo persistent per tile; V hi/lo doubles as Q staging before the loop.
    __shared__ __align__(16) __nv_bfloat16 sKh[BN * KP], sKl[BN * KP];
    __shared__ __align__(16) __nv_bfloat16 sVh[BN * KP], sVl[BN * KP];

    const int tid  = threadIdx.x;
    const int wid  = tid >> 5;
    const int lane = tid & 31;
    const int g    = lane >> 2;      // row within 8-row group
    const int tg   = lane & 3;       // threadgroup (col pair)
    const int h    = blockIdx.y;
    const int qt   = gridDim.x - 1 - blockIdx.x;   // longest CTAs first
    const int q0   = qt * BM;

    const uint32_t kh_b = smem_u32(sKh), kl_b = smem_u32(sKl);
    const uint32_t vh_b = smem_u32(sVh), vl_b = smem_u32(sVl);

    // ---- stage Q (scaled, split) into sVh/sVl, then pull frags to registers ----
    const float* qp = qkv + (size_t)h * HD;
    for (int i = tid; i < BM * HD / 4; i += NTHR) {
        int r = i >> 4, d4 = (i & 15) << 2;
        float4 v = *(const float4*)(qp + (size_t)(q0 + r) * TOKST + d4);
        uint32_t h0, l0, h1, l1;
        split2(v.x * QSCALE, v.y * QSCALE, h0, l0);
        split2(v.z * QSCALE, v.w * QSCALE, h1, l1);
        char* ph = (char*)sVh + r * KPB + d4 * 2;
        char* pl = (char*)sVl + r * KPB + d4 * 2;
        *(uint32_t*)ph = h0; *(uint32_t*)(ph + 4) = h1;
        *(uint32_t*)pl = l0; *(uint32_t*)(pl + 4) = l1;
    }
    __syncthreads();

    uint32_t Qh[4][4], Ql[4][4];
    {
        // A-frag x4 addressing: m0 rows r0..r0+7 / cols k0..k0+7, m1 rows+8, m2 cols+8, m3 both
        uint32_t aoff = (uint32_t)(wid * 16 + (lane & 7) + ((lane >> 3) & 1) * 8) * KPB
                      + (uint32_t)(lane >> 4) * 16;
        #pragma unroll
        for (int ks = 0; ks < 4; ks++) {
            LDSM4(Qh[ks], vh_b + aoff + ks * 32);
            LDSM4(Ql[ks], vl_b + aoff + ks * 32);
        }
    }
    __syncthreads();   // staging consumed; sVh/sVl free for V tiles

    float O[8][4];
    #pragma unroll
    for (int nt = 0; nt < 8; nt++)
        #pragma unroll
        for (int c = 0; c < 4; c++) O[nt][c] = 0.f;
    float m_i[2] = {-1e30f, -1e30f}, l_i[2] = {0.f, 0.f};

    const float* kp = qkv + (size_t)NH * HD     + (size_t)h * HD;
    const float* vp = qkv + (size_t)2 * NH * HD + (size_t)h * HD;

    // per-thread ldmatrix offsets
    const uint32_t kfrag_off = (uint32_t)(lane & 7) * KPB + (uint32_t)(lane >> 3) * 16;
    const uint32_t vfrag_row = (uint32_t)lane * KPB;   // row = half*32 + lane

    const int row0 = q0 + wid * 16 + g;   // this thread's first q-row
    const int row1 = row0 + 8;

    for (int kt = 0; kt <= qt; kt++) {
        const int k0 = kt * BN;

        // ---- load K,V fp32, split, store to smem ----
        for (int i = tid; i < BN * HD / 4; i += NTHR) {
            int r = i >> 4, d4 = (i & 15) << 2;
            size_t off = (size_t)(k0 + r) * TOKST + d4;
            float4 kv = *(const float4*)(kp + off);
            float4 vv = *(const float4*)(vp + off);
            uint32_t h0, l0, h1, l1;
            split2(kv.x, kv.y, h0, l0);
            split2(kv.z, kv.w, h1, l1);
            char* pkh = (char*)sKh + r * KPB + d4 * 2;
            char* pkl = (char*)sKl + r * KPB + d4 * 2;
            *(uint32_t*)pkh = h0; *(uint32_t*)(pkh + 4) = h1;
            *(uint32_t*)pkl = l0; *(uint32_t*)(pkl + 4) = l1;
            split2(vv.x, vv.y, h0, l0);
            split2(vv.z, vv.w, h1, l1);
            char* pvh = (char*)sVh + r * KPB + d4 * 2;
            char* pvl = (char*)sVl + r * KPB + d4 * 2;
            *(uint32_t*)pvh = h0; *(uint32_t*)(pvh + 4) = h1;
            *(uint32_t*)pvl = l0; *(uint32_t*)(pvl + 4) = l1;
        }
        __syncthreads();

        // ---- S = Q K^T, 8 n-tiles, 3-term split ----
        float S[8][4];
        #pragma unroll
        for (int nt = 0; nt < 8; nt++) {
            uint32_t bh[4][2], bl[4][2];
            uint32_t base = (uint32_t)nt * 8 * KPB + kfrag_off;
            LDSM4(&bh[0][0], kh_b + base);        // ks0,ks1 (cols 0..31)
            LDSM4(&bh[2][0], kh_b + base + 64);   // ks2,ks3 (cols 32..63)
            LDSM4(&bl[0][0], kl_b + base);
            LDSM4(&bl[2][0], kl_b + base + 64);
            #pragma unroll
            for (int c = 0; c < 4; c++) S[nt][c] = 0.f;
            #pragma unroll
            for (int ks = 0; ks < 4; ks++) {
                MMA(S[nt], Qh[ks], bh[ks]);
                MMA(S[nt], Qh[ks], bl[ks]);
                MMA(S[nt], Ql[ks], bh[ks]);
            }
        }

        // ---- causal mask (diagonal tile only) ----
        if (kt == qt) {
            #pragma unroll
            for (int nt = 0; nt < 8; nt++) {
                int colb = k0 + nt * 8 + 2 * tg;
                if (colb     > row0) S[nt][0] = -1e30f;
                if (colb + 1 > row0) S[nt][1] = -1e30f;
                if (colb     > row1) S[nt][2] = -1e30f;
                if (colb + 1 > row1) S[nt][3] = -1e30f;
            }
        }

        // ---- online softmax (rows spread over lane quads) ----
        float mx0 = -1e30f, mx1 = -1e30f;
        #pragma unroll
        for (int nt = 0; nt < 8; nt++) {
            mx0 = fmaxf(mx0, fmaxf(S[nt][0], S[nt][1]));
            mx1 = fmaxf(mx1, fmaxf(S[nt][2], S[nt][3]));
        }
        #pragma unroll
        for (int off = 1; off <= 2; off <<= 1) {
            mx0 = fmaxf(mx0, __shfl_xor_sync(0xffffffffu, mx0, off));
            mx1 = fmaxf(mx1, __shfl_xor_sync(0xffffffffu, mx1, off));
        }
        const float mn0 = fmaxf(m_i[0], mx0), mn1 = fmaxf(m_i[1], mx1);
        const float corr0 = ex2(m_i[0] - mn0), corr1 = ex2(m_i[1] - mn1);
        m_i[0] = mn0; m_i[1] = mn1;

        float rs0 = 0.f, rs1 = 0.f;
        #pragma unroll
        for (int nt = 0; nt < 8; nt++) {
            float p0 = ex2(S[nt][0] - mn0);
            float p1 = ex2(S[nt][1] - mn0);
            float p2 = ex2(S[nt][2] - mn1);
            float p3 = ex2(S[nt][3] - mn1);
            S[nt][0] = p0; S[nt][1] = p1; S[nt][2] = p2; S[nt][3] = p3;
            rs0 += p0 + p1; rs1 += p2 + p3;
        }
        #pragma unroll
        for (int off = 1; off <= 2; off <<= 1) {
            rs0 += __shfl_xor_sync(0xffffffffu, rs0, off);
            rs1 += __shfl_xor_sync(0xffffffffu, rs1, off);
        }
        l_i[0] = l_i[0] * corr0 + rs0;
        l_i[1] = l_i[1] * corr1 + rs1;
        #pragma unroll
        for (int nt = 0; nt < 8; nt++) {
            O[nt][0] *= corr0; O[nt][1] *= corr0;
            O[nt][2] *= corr1; O[nt][3] *= corr1;
        }

        // ---- repack S -> P A-frags (hi/lo), FA2 c->a pairing ----
        uint32_t Ph[4][4], Pl[4][4];
        #pragma unroll
        for (int ks = 0; ks < 4; ks++) {
            #pragma unroll
            for (int pos = 0; pos < 4; pos++) {
                int ti = 2 * ks + (pos >> 1);
                int cb = (pos & 1) * 2;
                split2(S[ti][cb], S[ti][cb + 1], Ph[ks][pos], Pl[ks][pos]);
            }
        }

        // ---- O += P V, 8 d-tiles, 3-term split ----
        #pragma unroll
        for (int nt = 0; nt < 8; nt++) {
            uint32_t bvh[4][2], bvl[4][2];
            uint32_t cb = (uint32_t)nt * 16;
            LDSM4T(&bvh[0][0], vh_b + vfrag_row + cb);              // keys 0..31
            LDSM4T(&bvh[2][0], vh_b + 32 * KPB + vfrag_row + cb);   // keys 32..63
            LDSM4T(&bvl[0][0], vl_b + vfrag_row + cb);
            LDSM4T(&bvl[2][0], vl_b + 32 * KPB + vfrag_row + cb);
            #pragma unroll
            for (int ks = 0; ks < 4; ks++) {
                MMA(O[nt], Ph[ks], bvh[ks]);
                MMA(O[nt], Ph[ks], bvl[ks]);
                MMA(O[nt], Pl[ks], bvh[ks]);
            }
        }
        __syncthreads();   // V/K smem consumed before next tile overwrites
    }

    // ---- epilogue ----
    const float inv0 = 1.f / l_i[0], inv1 = 1.f / l_i[1];
    float* o0 = out + ((size_t)row0 * NH + h) * HD;
    float* o1 = out + ((size_t)row1 * NH + h) * HD;
    #pragma unroll
    for (int nt = 0; nt < 8; nt++) {
        int d = nt * 8 + 2 * tg;
        float2 w0 = make_float2(O[nt][0] * inv0, O[nt][1] * inv0);
        float2 w1 = make_float2(O[nt][2] * inv1, O[nt][3] * inv1);
        *(float2*)(o0 + d) = w0;
        *(float2*)(o1 + d) = w1;
    }
}

extern "C" void kernel_launch(void* const* d_in, const int* in_sizes, int n_in,
                              void* d_out, int out_size) {
    (void)in_sizes; (void)n_in; (void)out_size;
    const float* qkv = (const float*)d_in[0];
    float* out = (float*)d_out;
    dim3 grid(SEQ / BM, NH);
    attn_mma_kernel<<<grid, NTHR>>>(qkv, out);
}